// round 4
// baseline (speedup 1.0000x reference)
#include <cuda_runtime.h>
#include <math.h>

// RITS recurrent imputation. B=1024, T=128, D=64, H=256.
// NT=1024: thread = (gate g in {i,g,f,o}, hidden col htid). Each thread owns
// ONE lstm gate column for all 8 batch rows -> 1 LDG + 4 FFMA2 per k.
// 32 warps/SM (occ 50%) hide L2 latency of weight streams.
// Gate combine via SMEM exchange aliased onto dead pre-GEMM scratch.

#define Bc 1024
#define Tc 128
#define Dc 64
#define Hc 256
#define MB 8
#define NT 1024

// shared layout (floats)
#define OF_TDHWT 0                      // 64x256 (transposed td_h_W)
#define OF_HISTW (OF_TDHWT + 16384)     // 256x64
#define OF_TXWT  (OF_HISTW + 16384)     // 64x64
#define OF_FRWT  (OF_TXWT + 4096)       // 64x64
#define OF_WCW   (OF_FRWT + 4096)       // 128x64
#define OF_BHS   (OF_WCW + 8192)        // 256
#define OF_BXS   (OF_BHS + 256)         // 64
#define OF_BHIST (OF_BXS + 64)          // 64
#define OF_BFR   (OF_BHIST + 64)        // 64
#define OF_BWC   (OF_BFR + 64)          // 64
#define OF_HT    (OF_BWC + 64)          // h_t[256][8]
#define OF_INPT  (OF_HT + 2048)         // inp_t[128][8]
#define OF_EX    (OF_INPT + 1024)       // 4096: x|m|d|xh|xc|gx|al pre-GEMM; exchange post-GEMM
#define SMEM_FLOATS (OF_EX + 4096)      // 56832 floats
#define SMEM_BYTES (SMEM_FLOATS * 4)    // 227,328 B

typedef unsigned long long u64;

__device__ __forceinline__ u64 pack2(float a, float b) {
    u64 r; asm("mov.b64 %0,{%1,%2};" : "=l"(r) : "f"(a), "f"(b)); return r;
}
__device__ __forceinline__ void unpack2(u64 v, float& a, float& b) {
    asm("mov.b64 {%0,%1},%2;" : "=f"(a), "=f"(b) : "l"(v));
}
__device__ __forceinline__ void fma2(u64& acc, u64 a, u64 b) {
    asm("fma.rn.f32x2 %0, %1, %2, %0;" : "+l"(acc) : "l"(a), "l"(b));
}
__device__ __forceinline__ float sigf(float x) {
    return __fdividef(1.0f, 1.0f + __expf(-x));
}

extern "C" __global__ void __launch_bounds__(NT, 1)
rits_kernel(const float* __restrict__ values, const float* __restrict__ masks,
            const float* __restrict__ deltas,
            const float* __restrict__ td_h_W, const float* __restrict__ td_h_b,
            const float* __restrict__ td_x_W, const float* __restrict__ td_x_b,
            const float* __restrict__ hist_W, const float* __restrict__ hist_b,
            const float* __restrict__ fr_W, const float* __restrict__ fr_b,
            const float* __restrict__ wc_W, const float* __restrict__ wc_b,
            const float* __restrict__ lstm_k, const float* __restrict__ lstm_rk,
            const float* __restrict__ lstm_b,
            const float* __restrict__ out_W, const float* __restrict__ out_b,
            float* __restrict__ out)
{
    extern __shared__ float sm[];
    float* tdhWT = sm + OF_TDHWT;
    float* histWs = sm + OF_HISTW;
    float* txWT = sm + OF_TXWT;
    float* frWT = sm + OF_FRWT;
    float* wcWs = sm + OF_WCW;
    float* bhs = sm + OF_BHS;
    float* bxs = sm + OF_BXS;
    float* bhist = sm + OF_BHIST;
    float* bfr = sm + OF_BFR;
    float* bwc = sm + OF_BWC;
    float* h_t = sm + OF_HT;            // [256][8]
    float* inp_t = sm + OF_INPT;        // [128][8]
    // pre-GEMM scratch inside EX
    float* x_s  = sm + OF_EX;           // 512
    float* m_s  = sm + OF_EX + 512;     // 512
    float* d_s  = sm + OF_EX + 1024;    // 512
    float* xh_s = sm + OF_EX + 1536;    // 512
    float* xc_s = sm + OF_EX + 2048;    // 512
    float* gx_s = sm + OF_EX + 2560;    // 512
    float* al_s = sm + OF_EX + 3072;    // 512
    // post-GEMM exchange (aliases the above; all dead by then)
    float* sigi = sm + OF_EX;           // 2048: sigma(i), later tanh(c)
    float* tgc  = sm + OF_EX + 2048;    // 2048: tanh(g)

    const int tid = threadIdx.x;
    const int gate = tid >> 8;          // 0:i 1:g 2:f 3:o
    const int htid = tid & 255;
    const int b0 = blockIdx.x * MB;

    // ---- preload small weights into SMEM ----
    for (int idx = tid; idx < Hc * Dc; idx += NT) {   // td_h_W [H,D] -> [D,H]
        int j = idx >> 6, k = idx & 63;
        tdhWT[k * Hc + j] = td_h_W[idx];
    }
    for (int idx = tid; idx < Hc * Dc; idx += NT)     // hist_W as-is
        histWs[idx] = hist_W[idx];
    for (int idx = tid; idx < Dc * Dc; idx += NT) {   // td_x_W -> T
        int i = idx >> 6, k = idx & 63;
        txWT[k * Dc + i] = td_x_W[idx];
    }
    for (int idx = tid; idx < Dc * Dc; idx += NT) {   // fr_W -> T
        int i = idx >> 6, k = idx & 63;
        frWT[k * Dc + i] = fr_W[idx];
    }
    for (int idx = tid; idx < 2 * Dc * Dc; idx += NT)
        wcWs[idx] = wc_W[idx];
    if (tid < 256) bhs[tid] = td_h_b[tid];
    if (tid >= 256 && tid < 320) {
        int q = tid - 256;
        bxs[q] = td_x_b[q];
        bhist[q] = hist_b[q];
        bfr[q] = fr_b[q];
        bwc[q] = wc_b[q];
    }
    for (int idx = tid; idx < Hc * MB; idx += NT) h_t[idx] = 0.0f;
    float c_reg[MB];                    // live only in gate==2 threads
    #pragma unroll
    for (int r = 0; r < MB; r++) c_reg[r] = 0.0f;
    __syncthreads();

    // lstm gate column for this thread (keras order i,f,g,o in z)
    const int goff = (gate == 0) ? 0 : (gate == 1) ? 512 : (gate == 2) ? 256 : 768;
    const int col = htid + goff;
    const float bls = lstm_b[col];

    const int rL = (tid >> 6) & 7;      // row slot for 512-thread phases
    const int iL = tid & 63;

    float* out_y = out;
    float* out_imp = out + Bc;

    for (int t = 0; t < Tc; t++) {
        // ---- phase 1: load x, m, d ----
        if (tid < 512) {
            long gi = ((long)(b0 + rL) * Tc + t) * Dc + iL;
            x_s[tid] = values[gi];
            m_s[tid] = masks[gi];
        } else {
            int e = tid - 512;
            long gi = ((long)(b0 + rL) * Tc + t) * Dc + iL;
            d_s[e] = deltas[gi];
        }
        __syncthreads();

        // ---- phase 2: gamma_h (scale h_t) for 2 rows; gamma_x for half threads ----
        {
            #pragma unroll
            for (int q = 0; q < 2; q++) {
                int r = gate + q * 4;
                float s = bhs[htid];
                #pragma unroll 16
                for (int k = 0; k < Dc; k++)
                    s += d_s[r * Dc + k] * tdhWT[k * Hc + htid];
                h_t[htid * MB + r] *= __expf(-fmaxf(s, 0.0f));
            }
            if (tid < 512) {
                float s2 = bxs[iL];
                #pragma unroll 16
                for (int k = 0; k < Dc; k++)
                    s2 += d_s[rL * Dc + k] * txWT[k * Dc + iL];
                gx_s[rL * Dc + iL] = __expf(-fmaxf(s2, 0.0f));
            }
        }
        __syncthreads();

        // ---- phase 3: x_h/x_c (threads<512) || alpha (threads>=512) ----
        if (tid < 512) {
            float s = bhist[iL];
            #pragma unroll 16
            for (int j = 0; j < Hc; j++)
                s += h_t[j * MB + rL] * histWs[j * Dc + iL];
            float mm = m_s[rL * Dc + iL];
            xh_s[rL * Dc + iL] = s;
            xc_s[rL * Dc + iL] = mm * x_s[rL * Dc + iL] + (1.0f - mm) * s;
        } else {
            float al = bwc[iL];
            #pragma unroll 16
            for (int k = 0; k < Dc; k++)
                al += gx_s[rL * Dc + k] * wcWs[k * Dc + iL];
            #pragma unroll 16
            for (int k = 0; k < Dc; k++)
                al += m_s[rL * Dc + k] * wcWs[(Dc + k) * Dc + iL];
            al_s[rL * Dc + iL] = al;
        }
        __syncthreads();

        // ---- phase 4: z_h, c_h, c_c, imputation, inp_t (threads<512) ----
        if (tid < 512) {
            float zh = bfr[iL];
            #pragma unroll 16
            for (int k = 0; k < Dc; k++)
                zh += xc_s[rL * Dc + k] * frWT[k * Dc + iL];
            float al = al_s[rL * Dc + iL];
            float ch = al * zh + (1.0f - al) * xh_s[rL * Dc + iL];
            float mm = m_s[rL * Dc + iL];
            float cc = mm * x_s[rL * Dc + iL] + (1.0f - mm) * ch;
            inp_t[iL * MB + rL] = cc;
            inp_t[(Dc + iL) * MB + rL] = mm;
            out_imp[((long)(b0 + rL) * Tc + t) * Dc + iL] = cc;
        }
        __syncthreads();

        // ---- phase 5: GEMM  z_col = [c_c|m] @ lstm_k[:,col] + h @ lstm_rk[:,col] + b ----
        u64 A[4];
        #pragma unroll
        for (int p = 0; p < 4; p++) A[p] = pack2(bls, bls);
        {
            const float* W = lstm_k + col;   // [128][1024]
            #pragma unroll 4
            for (int k = 0; k < 128; k++) {
                float w = __ldg(&W[k * 1024]);
                u64 ww = pack2(w, w);
                ulonglong2 v0 = *(const ulonglong2*)(inp_t + k * MB);
                ulonglong2 v1 = *(const ulonglong2*)(inp_t + k * MB + 4);
                fma2(A[0], v0.x, ww); fma2(A[1], v0.y, ww);
                fma2(A[2], v1.x, ww); fma2(A[3], v1.y, ww);
            }
            const float* Wr = lstm_rk + col; // [256][1024]
            #pragma unroll 4
            for (int k = 0; k < 256; k++) {
                float w = __ldg(&Wr[k * 1024]);
                u64 ww = pack2(w, w);
                ulonglong2 v0 = *(const ulonglong2*)(h_t + k * MB);
                ulonglong2 v1 = *(const ulonglong2*)(h_t + k * MB + 4);
                fma2(A[0], v0.x, ww); fma2(A[1], v0.y, ww);
                fma2(A[2], v1.x, ww); fma2(A[3], v1.y, ww);
            }
        }
        float z[8];
        unpack2(A[0], z[0], z[1]); unpack2(A[1], z[2], z[3]);
        unpack2(A[2], z[4], z[5]); unpack2(A[3], z[6], z[7]);

        // ---- gate exchange: i,g stage; f updates cell; o writes h ----
        if (gate == 0) {                      // sigma(i)
            float4 o0 = {sigf(z[0]), sigf(z[1]), sigf(z[2]), sigf(z[3])};
            float4 o1 = {sigf(z[4]), sigf(z[5]), sigf(z[6]), sigf(z[7])};
            *(float4*)(sigi + htid * MB) = o0;
            *(float4*)(sigi + htid * MB + 4) = o1;
        } else if (gate == 1) {               // tanh(g)
            float4 o0 = {tanhf(z[0]), tanhf(z[1]), tanhf(z[2]), tanhf(z[3])};
            float4 o1 = {tanhf(z[4]), tanhf(z[5]), tanhf(z[6]), tanhf(z[7])};
            *(float4*)(tgc + htid * MB) = o0;
            *(float4*)(tgc + htid * MB + 4) = o1;
        }
        __syncthreads();
        if (gate == 2) {                      // f: c = sig(f)*c + sig(i)*tanh(g)
            float4 s0 = *(const float4*)(sigi + htid * MB);
            float4 s1 = *(const float4*)(sigi + htid * MB + 4);
            float4 g0 = *(const float4*)(tgc + htid * MB);
            float4 g1 = *(const float4*)(tgc + htid * MB + 4);
            float si[8] = {s0.x, s0.y, s0.z, s0.w, s1.x, s1.y, s1.z, s1.w};
            float tg[8] = {g0.x, g0.y, g0.z, g0.w, g1.x, g1.y, g1.z, g1.w};
            float tc[8];
            #pragma unroll
            for (int r = 0; r < MB; r++) {
                float cn = sigf(z[r]) * c_reg[r] + si[r] * tg[r];
                c_reg[r] = cn;
                tc[r] = tanhf(cn);
            }
            float4 t0 = {tc[0], tc[1], tc[2], tc[3]};
            float4 t1 = {tc[4], tc[5], tc[6], tc[7]};
            *(float4*)(sigi + htid * MB) = t0;      // same addrs it just read
            *(float4*)(sigi + htid * MB + 4) = t1;
        }
        __syncthreads();
        if (gate == 3) {                      // o: h = sig(o)*tanh(c)
            float4 t0 = *(const float4*)(sigi + htid * MB);
            float4 t1 = *(const float4*)(sigi + htid * MB + 4);
            float tc[8] = {t0.x, t0.y, t0.z, t0.w, t1.x, t1.y, t1.z, t1.w};
            float hv[8];
            #pragma unroll
            for (int r = 0; r < MB; r++) hv[r] = sigf(z[r]) * tc[r];
            float4 h0 = {hv[0], hv[1], hv[2], hv[3]};
            float4 h1 = {hv[4], hv[5], hv[6], hv[7]};
            *(float4*)(h_t + htid * MB) = h0;
            *(float4*)(h_t + htid * MB + 4) = h1;
        }
        __syncthreads();
    }

    // ---- y = h @ out_W + out_b ----
    {
        float* red = sigi;  // scratch
        float ow = (tid < 256) ? __ldg(&out_W[tid]) : 0.0f;
        int lane = tid & 31, w = tid >> 5;  // 32 warps
        for (int r = 0; r < MB; r++) {
            float v = (tid < 256) ? h_t[tid * MB + r] * ow : 0.0f;
            #pragma unroll
            for (int off = 16; off > 0; off >>= 1)
                v += __shfl_xor_sync(0xffffffffu, v, off);
            if (lane == 0) red[w] = v;
            __syncthreads();
            if (tid == 0) {
                float s = out_b[0];
                #pragma unroll
                for (int q = 0; q < 32; q++) s += red[q];
                out_y[b0 + r] = s;
            }
            __syncthreads();
        }
    }
}

extern "C" void kernel_launch(void* const* d_in, const int* in_sizes, int n_in,
                              void* d_out, int out_size)
{
    const float* values = (const float*)d_in[0];
    const float* masks  = (const float*)d_in[1];
    const float* deltas = (const float*)d_in[2];
    const float* td_h_W = (const float*)d_in[3];
    const float* td_h_b = (const float*)d_in[4];
    const float* td_x_W = (const float*)d_in[5];
    const float* td_x_b = (const float*)d_in[6];
    const float* hist_W = (const float*)d_in[7];
    const float* hist_b = (const float*)d_in[8];
    const float* fr_W   = (const float*)d_in[9];
    const float* fr_b   = (const float*)d_in[10];
    const float* wc_W   = (const float*)d_in[11];
    const float* wc_b   = (const float*)d_in[12];
    const float* lstm_k  = (const float*)d_in[13];
    const float* lstm_rk = (const float*)d_in[14];
    const float* lstm_b  = (const float*)d_in[15];
    const float* out_W  = (const float*)d_in[16];
    const float* out_b  = (const float*)d_in[17];
    float* out = (float*)d_out;

    static bool attr_set = false;
    if (!attr_set) {
        cudaFuncSetAttribute(rits_kernel,
                             cudaFuncAttributeMaxDynamicSharedMemorySize, SMEM_BYTES);
        attr_set = true;
    }
    rits_kernel<<<Bc / MB, NT, SMEM_BYTES>>>(
        values, masks, deltas, td_h_W, td_h_b, td_x_W, td_x_b,
        hist_W, hist_b, fr_W, fr_b, wc_W, wc_b,
        lstm_k, lstm_rk, lstm_b, out_W, out_b, out);
}

// round 6
// speedup vs baseline: 1.3341x; 1.3341x over previous
#include <cuda_runtime.h>
#include <math.h>

// RITS recurrent imputation. B=1024, T=128, D=64, H=256.
// NT=512: GEMM thread = (gate, col-pair). One LDG.64 weight load per k
// feeds 8 FFMA2 (2 cols x 8 rows packed). Small phases use f32x2-packed
// dots over k-pair-interleaved SMEM weights. 16 warps/SM, 1 CTA/SM.

#define Bc 1024
#define Tc 128
#define Dc 64
#define Hc 256
#define MB 8
#define NT 512

// shared layout (floats)
#define OF_TDHW2 0                       // [32 k2][256 col][2]
#define OF_HISTW (OF_TDHW2 + 16384)      // [256 j][64 i]
#define OF_TXW2  (OF_HISTW + 16384)      // [32 k2][64 i][2]
#define OF_FRW2  (OF_TXW2 + 4096)        // [32 k2][64 i][2]
#define OF_WCW2  (OF_FRW2 + 4096)        // [64 k2][64 i][2]
#define OF_BHS   (OF_WCW2 + 8192)        // 256
#define OF_BXS   (OF_BHS + 256)          // 64
#define OF_BHIST (OF_BXS + 64)           // 64
#define OF_BFR   (OF_BHIST + 64)         // 64
#define OF_BWC   (OF_BFR + 64)           // 64
#define OF_HT    (OF_BWC + 64)           // h_t[256][8]
#define OF_INPT  (OF_HT + 2048)          // inp_t[128][8]
#define OF_EX    (OF_INPT + 1024)        // 4096 scratch / exchange
#define SMEM_FLOATS (OF_EX + 4096)       // 56832
#define SMEM_BYTES (SMEM_FLOATS * 4)     // 227,328 B

typedef unsigned long long u64;

__device__ __forceinline__ u64 pack2(float a, float b) {
    u64 r; asm("mov.b64 %0,{%1,%2};" : "=l"(r) : "f"(a), "f"(b)); return r;
}
__device__ __forceinline__ void unpack2(u64 v, float& a, float& b) {
    asm("mov.b64 {%0,%1},%2;" : "=f"(a), "=f"(b) : "l"(v));
}
__device__ __forceinline__ void fma2(u64& acc, u64 a, u64 b) {
    asm("fma.rn.f32x2 %0, %1, %2, %0;" : "+l"(acc) : "l"(a), "l"(b));
}
__device__ __forceinline__ float sigf(float x) {
    return __fdividef(1.0f, 1.0f + __expf(-x));
}

extern "C" __global__ void __launch_bounds__(NT, 1)
rits_kernel(const float* __restrict__ values, const float* __restrict__ masks,
            const float* __restrict__ deltas,
            const float* __restrict__ td_h_W, const float* __restrict__ td_h_b,
            const float* __restrict__ td_x_W, const float* __restrict__ td_x_b,
            const float* __restrict__ hist_W, const float* __restrict__ hist_b,
            const float* __restrict__ fr_W, const float* __restrict__ fr_b,
            const float* __restrict__ wc_W, const float* __restrict__ wc_b,
            const float* __restrict__ lstm_k, const float* __restrict__ lstm_rk,
            const float* __restrict__ lstm_b,
            const float* __restrict__ out_W, const float* __restrict__ out_b,
            float* __restrict__ out)
{
    extern __shared__ float sm[];
    float* tdhW2 = sm + OF_TDHW2;
    float* histWs = sm + OF_HISTW;
    float* txW2 = sm + OF_TXW2;
    float* frW2 = sm + OF_FRW2;
    float* wcW2 = sm + OF_WCW2;
    float* bhs = sm + OF_BHS;
    float* bxs = sm + OF_BXS;
    float* bhist = sm + OF_BHIST;
    float* bfr = sm + OF_BFR;
    float* bwc = sm + OF_BWC;
    float* h_t = sm + OF_HT;            // [256][8]
    float* inp_t = sm + OF_INPT;        // [128][8]
    // pre-GEMM scratch inside EX
    float* x_s  = sm + OF_EX;           // 512
    float* m_s  = sm + OF_EX + 512;     // 512
    float* d_s  = sm + OF_EX + 1024;    // 512
    float* xh_s = sm + OF_EX + 1536;    // 512
    float* xc_s = sm + OF_EX + 2048;    // 512
    float* gx_s = sm + OF_EX + 2560;    // 512
    float* al_s = sm + OF_EX + 3072;    // 512
    // post-GEMM exchange (aliases scratch; staged so phase1 never races)
    float* sigi = sm + OF_EX;           // 2048: sigma(i) staging
    float* tgc  = sm + OF_EX + 2048;    // 2048: tanh(g), then tanh(c)

    const int tid = threadIdx.x;
    const int b0 = blockIdx.x * MB;

    // ---- preload + repack small weights into SMEM ----
    for (int idx = tid; idx < 16384; idx += NT) {     // td_h_W -> k-pair interleave
        int k2 = idx >> 9, rem = idx & 511, col = rem >> 1, s = rem & 1;
        tdhW2[idx] = td_h_W[col * Dc + 2 * k2 + s];
    }
    for (int idx = tid; idx < Hc * Dc; idx += NT)     // hist_W as-is
        histWs[idx] = hist_W[idx];
    for (int idx = tid; idx < 4096; idx += NT) {      // td_x_W
        int k2 = idx >> 7, rem = idx & 127, i = rem >> 1, s = rem & 1;
        txW2[idx] = td_x_W[i * Dc + 2 * k2 + s];
    }
    for (int idx = tid; idx < 4096; idx += NT) {      // fr_W
        int k2 = idx >> 7, rem = idx & 127, i = rem >> 1, s = rem & 1;
        frW2[idx] = fr_W[i * Dc + 2 * k2 + s];
    }
    for (int idx = tid; idx < 8192; idx += NT) {      // wc_W
        int k2 = idx >> 7, rem = idx & 127, i = rem >> 1, s = rem & 1;
        wcW2[idx] = wc_W[(2 * k2 + s) * Dc + i];
    }
    if (tid < 256) bhs[tid] = td_h_b[tid];
    if (tid >= 256 && tid < 320) {
        int q = tid - 256;
        bxs[q] = td_x_b[q];
        bhist[q] = hist_b[q];
        bfr[q] = fr_b[q];
        bwc[q] = wc_b[q];
    }
    for (int idx = tid; idx < Hc * MB; idx += NT) h_t[idx] = 0.0f;

    // GEMM thread mapping: gate group (128 threads each), adjacent col pair
    const int g = tid >> 7;             // 0:i 1:g 2:f 3:o
    const int hh = tid & 127;
    const int goff = (g == 0) ? 0 : (g == 1) ? 512 : (g == 2) ? 256 : 768;
    const int col0 = goff + 2 * hh;
    const float bl0 = lstm_b[col0];
    const float bl1 = lstm_b[col0 + 1];

    float c0[MB], c1[MB];               // cell state (live in f-group only)
    #pragma unroll
    for (int r = 0; r < MB; r++) { c0[r] = 0.0f; c1[r] = 0.0f; }

    const int rL = (tid >> 6) & 7;      // row slot
    const int iL = tid & 63;            // feature col
    const int colh = tid & 255;         // gamma_h column
    const int rbase = (tid >> 8) * 4;   // gamma_h row base

    float* out_y = out;
    float* out_imp = out + Bc;

    // prefetch t=0 inputs
    long gi0 = ((long)(b0 + rL) * Tc) * Dc + iL;
    float nx = values[gi0], nm = masks[gi0], nd = deltas[gi0];
    __syncthreads();

    for (int t = 0; t < Tc; t++) {
        // ---- phase 1: store prefetched x, m, d ----
        x_s[tid] = nx; m_s[tid] = nm; d_s[tid] = nd;
        __syncthreads();

        // ---- phase 2: gamma_h (scale h_t, 4 rows) + gamma_x ----
        {
            #pragma unroll
            for (int q = 0; q < 4; q++) {
                int r = rbase + q;
                const u64* dp = (const u64*)(d_s + r * Dc);
                u64 acc = 0;
                #pragma unroll 8
                for (int k2 = 0; k2 < 32; k2++)
                    fma2(acc, dp[k2], *(const u64*)(tdhW2 + k2 * 512 + colh * 2));
                float a, b; unpack2(acc, a, b);
                float s = bhs[colh] + a + b;
                h_t[colh * MB + r] *= __expf(-fmaxf(s, 0.0f));
            }
            const u64* dp = (const u64*)(d_s + rL * Dc);
            u64 acc = 0;
            #pragma unroll 8
            for (int k2 = 0; k2 < 32; k2++)
                fma2(acc, dp[k2], *(const u64*)(txW2 + k2 * 128 + iL * 2));
            float a, b; unpack2(acc, a, b);
            gx_s[rL * Dc + iL] = __expf(-fmaxf(bxs[iL] + a + b, 0.0f));
        }
        __syncthreads();

        // ---- phase 3: x_h/x_c + alpha ----
        {
            float s = bhist[iL];
            #pragma unroll 16
            for (int j = 0; j < Hc; j++)
                s += h_t[j * MB + rL] * histWs[j * Dc + iL];
            float mm = m_s[rL * Dc + iL];
            xh_s[rL * Dc + iL] = s;
            xc_s[rL * Dc + iL] = mm * x_s[rL * Dc + iL] + (1.0f - mm) * s;

            const u64* gp = (const u64*)(gx_s + rL * Dc);
            const u64* mp = (const u64*)(m_s + rL * Dc);
            u64 acc = 0;
            #pragma unroll 8
            for (int k2 = 0; k2 < 32; k2++)
                fma2(acc, gp[k2], *(const u64*)(wcW2 + k2 * 128 + iL * 2));
            #pragma unroll 8
            for (int k2 = 0; k2 < 32; k2++)
                fma2(acc, mp[k2], *(const u64*)(wcW2 + (32 + k2) * 128 + iL * 2));
            float a, b; unpack2(acc, a, b);
            al_s[rL * Dc + iL] = bwc[iL] + a + b;
        }
        __syncthreads();

        // ---- phase 4: z_h, c_h, c_c, imputation, inp_t ----
        {
            const u64* xp = (const u64*)(xc_s + rL * Dc);
            u64 acc = 0;
            #pragma unroll 8
            for (int k2 = 0; k2 < 32; k2++)
                fma2(acc, xp[k2], *(const u64*)(frW2 + k2 * 128 + iL * 2));
            float a, b; unpack2(acc, a, b);
            float zh = bfr[iL] + a + b;
            float al = al_s[rL * Dc + iL];
            float ch = al * zh + (1.0f - al) * xh_s[rL * Dc + iL];
            float mm = m_s[rL * Dc + iL];
            float cc = mm * x_s[rL * Dc + iL] + (1.0f - mm) * ch;
            inp_t[iL * MB + rL] = cc;
            inp_t[(Dc + iL) * MB + rL] = mm;
            out_imp[((long)(b0 + rL) * Tc + t) * Dc + iL] = cc;
        }
        __syncthreads();

        // prefetch next step's inputs (hidden under the GEMM)
        if (t + 1 < Tc) {
            long gi = ((long)(b0 + rL) * Tc + (t + 1)) * Dc + iL;
            nx = values[gi]; nm = masks[gi]; nd = deltas[gi];
        }

        // ---- phase 5: GEMM  z[col0,col0+1] over 8 rows ----
        u64 A0[4], A1[4];
        #pragma unroll
        for (int p = 0; p < 4; p++) { A0[p] = pack2(bl0, bl0); A1[p] = pack2(bl1, bl1); }
        {
            const float2* Wk = (const float2*)(lstm_k) + (col0 >> 1);  // [128][512]
            #pragma unroll 8
            for (int k = 0; k < 128; k++) {
                float2 w = __ldg(Wk + k * 512);
                u64 wx = pack2(w.x, w.x), wy = pack2(w.y, w.y);
                ulonglong2 v0 = *(const ulonglong2*)(inp_t + k * MB);
                ulonglong2 v1 = *(const ulonglong2*)(inp_t + k * MB + 4);
                fma2(A0[0], v0.x, wx); fma2(A0[1], v0.y, wx);
                fma2(A0[2], v1.x, wx); fma2(A0[3], v1.y, wx);
                fma2(A1[0], v0.x, wy); fma2(A1[1], v0.y, wy);
                fma2(A1[2], v1.x, wy); fma2(A1[3], v1.y, wy);
            }
            const float2* Wr = (const float2*)(lstm_rk) + (col0 >> 1); // [256][512]
            #pragma unroll 8
            for (int k = 0; k < 256; k++) {
                float2 w = __ldg(Wr + k * 512);
                u64 wx = pack2(w.x, w.x), wy = pack2(w.y, w.y);
                ulonglong2 v0 = *(const ulonglong2*)(h_t + k * MB);
                ulonglong2 v1 = *(const ulonglong2*)(h_t + k * MB + 4);
                fma2(A0[0], v0.x, wx); fma2(A0[1], v0.y, wx);
                fma2(A0[2], v1.x, wx); fma2(A0[3], v1.y, wx);
                fma2(A1[0], v0.x, wy); fma2(A1[1], v0.y, wy);
                fma2(A1[2], v1.x, wy); fma2(A1[3], v1.y, wy);
            }
        }
        float z0[8], z1[8];
        unpack2(A0[0], z0[0], z0[1]); unpack2(A0[1], z0[2], z0[3]);
        unpack2(A0[2], z0[4], z0[5]); unpack2(A0[3], z0[6], z0[7]);
        unpack2(A1[0], z1[0], z1[1]); unpack2(A1[1], z1[2], z1[3]);
        unpack2(A1[2], z1[4], z1[5]); unpack2(A1[3], z1[6], z1[7]);

        // ---- gate exchange ----
        if (g == 0) {                          // sigma(i) -> sigi
            float4 o0 = {sigf(z0[0]), sigf(z0[1]), sigf(z0[2]), sigf(z0[3])};
            float4 o1 = {sigf(z0[4]), sigf(z0[5]), sigf(z0[6]), sigf(z0[7])};
            float4 o2 = {sigf(z1[0]), sigf(z1[1]), sigf(z1[2]), sigf(z1[3])};
            float4 o3 = {sigf(z1[4]), sigf(z1[5]), sigf(z1[6]), sigf(z1[7])};
            float4* dst = (float4*)(sigi + hh * 16);
            dst[0] = o0; dst[1] = o1; dst[2] = o2; dst[3] = o3;
        } else if (g == 1) {                   // tanh(g) -> tgc
            float4 o0 = {tanhf(z0[0]), tanhf(z0[1]), tanhf(z0[2]), tanhf(z0[3])};
            float4 o1 = {tanhf(z0[4]), tanhf(z0[5]), tanhf(z0[6]), tanhf(z0[7])};
            float4 o2 = {tanhf(z1[0]), tanhf(z1[1]), tanhf(z1[2]), tanhf(z1[3])};
            float4 o3 = {tanhf(z1[4]), tanhf(z1[5]), tanhf(z1[6]), tanhf(z1[7])};
            float4* dst = (float4*)(tgc + hh * 16);
            dst[0] = o0; dst[1] = o1; dst[2] = o2; dst[3] = o3;
        }
        __syncthreads();
        if (g == 2) {                          // f: c = sig(f)*c + si*tg; tanh(c) -> tgc
            const float4* sp = (const float4*)(sigi + hh * 16);
            float4* gp4 = (float4*)(tgc + hh * 16);
            float4 s0 = sp[0], s1 = sp[1], s2 = sp[2], s3 = sp[3];
            float4 g0 = gp4[0], g1 = gp4[1], g2 = gp4[2], g3 = gp4[3];
            float si[16] = {s0.x, s0.y, s0.z, s0.w, s1.x, s1.y, s1.z, s1.w,
                            s2.x, s2.y, s2.z, s2.w, s3.x, s3.y, s3.z, s3.w};
            float tg[16] = {g0.x, g0.y, g0.z, g0.w, g1.x, g1.y, g1.z, g1.w,
                            g2.x, g2.y, g2.z, g2.w, g3.x, g3.y, g3.z, g3.w};
            float tc[16];
            #pragma unroll
            for (int r = 0; r < MB; r++) {
                float cn = sigf(z0[r]) * c0[r] + si[r] * tg[r];
                c0[r] = cn; tc[r] = tanhf(cn);
            }
            #pragma unroll
            for (int r = 0; r < MB; r++) {
                float cn = sigf(z1[r]) * c1[r] + si[8 + r] * tg[8 + r];
                c1[r] = cn; tc[8 + r] = tanhf(cn);
            }
            float4 t0 = {tc[0], tc[1], tc[2], tc[3]};
            float4 t1 = {tc[4], tc[5], tc[6], tc[7]};
            float4 t2 = {tc[8], tc[9], tc[10], tc[11]};
            float4 t3 = {tc[12], tc[13], tc[14], tc[15]};
            gp4[0] = t0; gp4[1] = t1; gp4[2] = t2; gp4[3] = t3;
        }
        __syncthreads();
        if (g == 3) {                          // o: h = sig(o)*tanh(c) -> h_t
            const float4* tp = (const float4*)(tgc + hh * 16);
            float4 t0 = tp[0], t1 = tp[1], t2 = tp[2], t3 = tp[3];
            float tc[16] = {t0.x, t0.y, t0.z, t0.w, t1.x, t1.y, t1.z, t1.w,
                            t2.x, t2.y, t2.z, t2.w, t3.x, t3.y, t3.z, t3.w};
            float hv[16];
            #pragma unroll
            for (int r = 0; r < MB; r++) hv[r] = sigf(z0[r]) * tc[r];
            #pragma unroll
            for (int r = 0; r < MB; r++) hv[8 + r] = sigf(z1[r]) * tc[8 + r];
            float4* dst = (float4*)(h_t + hh * 16);  // cols (2hh, 2hh+1)
            float4 h0 = {hv[0], hv[1], hv[2], hv[3]};
            float4 h1 = {hv[4], hv[5], hv[6], hv[7]};
            float4 h2 = {hv[8], hv[9], hv[10], hv[11]};
            float4 h3 = {hv[12], hv[13], hv[14], hv[15]};
            dst[0] = h0; dst[1] = h1; dst[2] = h2; dst[3] = h3;
        }
        // o's h_t writes + everyone's next phase-1 STS ordered by loop-top sync
        __syncthreads();
    }

    // ---- y = h @ out_W + out_b ----
    {
        float* red = sigi;  // scratch (loop done)
        float ow = (tid < 256) ? __ldg(&out_W[tid]) : 0.0f;
        int lane = tid & 31, w = tid >> 5;  // 16 warps
        for (int r = 0; r < MB; r++) {
            float v = (tid < 256) ? h_t[tid * MB + r] * ow : 0.0f;
            #pragma unroll
            for (int off = 16; off > 0; off >>= 1)
                v += __shfl_xor_sync(0xffffffffu, v, off);
            if (lane == 0) red[w] = v;
            __syncthreads();
            if (tid == 0) {
                float s = out_b[0];
                #pragma unroll
                for (int q = 0; q < 16; q++) s += red[q];
                out_y[b0 + r] = s;
            }
            __syncthreads();
        }
    }
}

extern "C" void kernel_launch(void* const* d_in, const int* in_sizes, int n_in,
                              void* d_out, int out_size)
{
    const float* values = (const float*)d_in[0];
    const float* masks  = (const float*)d_in[1];
    const float* deltas = (const float*)d_in[2];
    const float* td_h_W = (const float*)d_in[3];
    const float* td_h_b = (const float*)d_in[4];
    const float* td_x_W = (const float*)d_in[5];
    const float* td_x_b = (const float*)d_in[6];
    const float* hist_W = (const float*)d_in[7];
    const float* hist_b = (const float*)d_in[8];
    const float* fr_W   = (const float*)d_in[9];
    const float* fr_b   = (const float*)d_in[10];
    const float* wc_W   = (const float*)d_in[11];
    const float* wc_b   = (const float*)d_in[12];
    const float* lstm_k  = (const float*)d_in[13];
    const float* lstm_rk = (const float*)d_in[14];
    const float* lstm_b  = (const float*)d_in[15];
    const float* out_W  = (const float*)d_in[16];
    const float* out_b  = (const float*)d_in[17];
    float* out = (float*)d_out;

    static bool attr_set = false;
    if (!attr_set) {
        cudaFuncSetAttribute(rits_kernel,
                             cudaFuncAttributeMaxDynamicSharedMemorySize, SMEM_BYTES);
        attr_set = true;
    }
    rits_kernel<<<Bc / MB, NT, SMEM_BYTES>>>(
        values, masks, deltas, td_h_W, td_h_b, td_x_W, td_x_b,
        hist_W, hist_b, fr_W, fr_b, wc_W, wc_b,
        lstm_k, lstm_rk, lstm_b, out_W, out_b, out);
}